// round 1
// baseline (speedup 1.0000x reference)
#include <cuda_runtime.h>

// Problem constants (shapes fixed by the benchmark: [32,128,32,32], kern=2)
#define BB 32
#define CC 128
#define HH 32
#define WW 32
#define PH 16   // pooled height
#define PW 16   // pooled width
#define NPOS (CC * PH * PW)          // 32768 positions
#define WARPS_PER_BLOCK 8
#define NBLOCKS (NPOS / WARPS_PER_BLOCK)  // 4096

__device__ double g_partials[NBLOCKS];

__device__ __forceinline__ float ex2f(float x) {
    float r; asm("ex2.approx.f32 %0, %1;" : "=f"(r) : "f"(x)); return r;
}
__device__ __forceinline__ float lg2f(float x) {
    float r; asm("lg2.approx.f32 %0, %1;" : "=f"(r) : "f"(x)); return r;
}

__global__ __launch_bounds__(WARPS_PER_BLOCK * 32)
void gkl_main_kernel(const float* __restrict__ mu_a,
                     const float* __restrict__ lva,
                     const float* __restrict__ mu_b,
                     const float* __restrict__ lvb,
                     const float* __restrict__ eps)
{
    __shared__ float4 shA[WARPS_PER_BLOCK][BB];
    __shared__ float4 shB[WARPS_PER_BLOCK][BB];
    __shared__ float warp_part[WARPS_PER_BLOCK];

    const int warp = threadIdx.x >> 5;
    const int lane = threadIdx.x & 31;
    const int p = blockIdx.x * WARPS_PER_BLOCK + warp;   // position id
    const int c = p >> 8;          // p / (PH*PW)
    const int y = (p >> 4) & 15;
    const int x = p & 15;

    // ---------------- Phase 1: lane = batch index b ----------------
    // 2x2 pooling window at (2y, 2x) for channel c, batch `lane`.
    const int base = ((lane * CC + c) * HH + 2 * y) * WW + 2 * x;

    float2 a0 = *(const float2*)(mu_a + base);
    float2 a1 = *(const float2*)(mu_a + base + WW);
    float m_a = 0.25f * ((a0.x + a0.y) + (a1.x + a1.y));

    float2 la0 = *(const float2*)(lva + base);
    float2 la1 = *(const float2*)(lva + base + WW);
    // var_a = avgpool(exp(logvar))/k^2 = (sum of 4 exps)/16
    float v_a = 0.0625f * ((__expf(la0.x) + __expf(la0.y)) +
                           (__expf(la1.x) + __expf(la1.y)));

    float2 b0 = *(const float2*)(mu_b + base);
    float2 b1 = *(const float2*)(mu_b + base + WW);
    float m_b = 0.25f * ((b0.x + b0.y) + (b1.x + b1.y));

    float2 lb0 = *(const float2*)(lvb + base);
    float2 lb1 = *(const float2*)(lvb + base + WW);
    float v_b = 0.0625f * ((__expf(lb0.x) + __expf(lb0.y)) +
                           (__expf(lb1.x) + __expf(lb1.y)));

    float e = eps[((lane * CC + c) * PH + y) * PW + x];

    const float NHALF_LOG2E = -0.7213475204444817f;  // -log2(e)/2
    float wa  = rsqrtf(v_a);                 // 1/sqrt(var_a)
    float z   = fmaf(v_a * wa, e, m_a);      // mu_a + sqrt(var_a)*eps
    float c1a = NHALF_LOG2E * wa * wa;       // -log2(e)/(2 var_a)
    float wb  = rsqrtf(v_b);
    float c1b = NHALF_LOG2E * wb * wb;

    shA[warp][lane] = make_float4(m_a, c1a, wa, 0.f);
    shB[warp][lane] = make_float4(m_b, c1b, wb, 0.f);
    __syncwarp();

    // ---------------- Phase 2: lane = sample index i ----------------
    // sum_j w_j * exp(-(z_i - mu_j)^2 / (2 var_j))   for both mixtures
    float sa = 0.f, sb = 0.f;
    #pragma unroll
    for (int j = 0; j < BB; j++) {
        float4 pa = shA[warp][j];    // broadcast LDS.128
        float4 pb = shB[warp][j];
        float da = z - pa.x;
        sa = fmaf(pa.z, ex2f((da * pa.y) * da), sa);
        float db = z - pb.x;
        sb = fmaf(pb.z, ex2f((db * pb.y) * db), sb);
    }

    const float LN2  = 0.6931471805599453f;
    const float EPSC = 1e-6f;
    const float INV_B = 1.0f / (float)BB;
    float term = (lg2f(fmaf(sa, INV_B, EPSC)) -
                  lg2f(fmaf(sb, INV_B, EPSC))) * LN2;

    // warp tree-reduce (fixed order -> deterministic)
    #pragma unroll
    for (int o = 16; o; o >>= 1)
        term += __shfl_xor_sync(0xFFFFFFFFu, term, o);

    if (lane == 0) warp_part[warp] = term;
    __syncthreads();
    if (threadIdx.x == 0) {
        double s = 0.0;
        #pragma unroll
        for (int w0 = 0; w0 < WARPS_PER_BLOCK; w0++)
            s += (double)warp_part[w0];
        g_partials[blockIdx.x] = s;
    }
}

__global__ void gkl_finalize(float* __restrict__ out)
{
    __shared__ double sh[256];
    double s = 0.0;
    for (int i = threadIdx.x; i < NBLOCKS; i += 256)
        s += g_partials[i];
    sh[threadIdx.x] = s;
    __syncthreads();
    #pragma unroll
    for (int o = 128; o; o >>= 1) {
        if (threadIdx.x < o) sh[threadIdx.x] += sh[threadIdx.x + o];
        __syncthreads();
    }
    if (threadIdx.x == 0)
        out[0] = (float)((double)BB * sh[0]);
}

extern "C" void kernel_launch(void* const* d_in, const int* in_sizes, int n_in,
                              void* d_out, int out_size)
{
    const float* mu_a = (const float*)d_in[0];
    const float* lva  = (const float*)d_in[1];
    const float* mu_b = (const float*)d_in[2];
    const float* lvb  = (const float*)d_in[3];
    const float* eps  = (const float*)d_in[4];
    // d_in[5] = kern (int), fixed to 2 for this problem's shapes.

    gkl_main_kernel<<<NBLOCKS, WARPS_PER_BLOCK * 32>>>(mu_a, lva, mu_b, lvb, eps);
    gkl_finalize<<<1, 256>>>((float*)d_out);
}

// round 3
// speedup vs baseline: 1.3706x; 1.3706x over previous
#include <cuda_runtime.h>

// Shapes fixed by the benchmark: [32,128,32,32], kern=2
#define BB 32
#define CC 128
#define HH 32
#define WW 32
#define PH 16
#define PW 16
#define NBLOCKS (CC * PH)        // 2048 blocks, one per (c, y)
#define NTHREADS 512             // 16 warps: warp = x in phase 2

__device__ double g_partials[NBLOCKS];
__device__ unsigned int g_count = 0;

__device__ __forceinline__ float ex2f(float x) {
    float r; asm("ex2.approx.f32 %0, %1;" : "=f"(r) : "f"(x)); return r;
}
__device__ __forceinline__ float lg2f(float x) {
    float r; asm("lg2.approx.f32 %0, %1;" : "=f"(r) : "f"(x)); return r;
}

__global__ __launch_bounds__(NTHREADS)
void gkl_kernel(const float* __restrict__ mu_a,
                const float* __restrict__ lva,
                const float* __restrict__ mu_b,
                const float* __restrict__ lvb,
                const float* __restrict__ eps,
                float* __restrict__ out)
{
    // pooled[t][b][x]: t=0 mu_a, 1 var_a, 2 mu_b, 3 var_b
    __shared__ float  pooled[4][BB][PW];     // 8 KB
    __shared__ float4 pA[PW][BB];            // 8 KB  (p, q, r, w) mixture a
    __shared__ float4 pB[PW][BB];            // 8 KB
    __shared__ float  zs[PW][BB];            // 2 KB
    __shared__ float  wsum[16];
    __shared__ int    is_last_s;
    __shared__ double dred[NTHREADS];        // 4 KB (finalize only)

    const int tid  = threadIdx.x;
    const int warp = tid >> 5;               // 0..15
    const int lane = tid & 31;
    const int c = blockIdx.x >> 4;
    const int y = blockIdx.x & 15;

    // ---------- Phase 1a: coalesced loads + pair pooling ----------
    // Task (tensor t, batch b): warp loads rows 2y and 2y+1 (32 floats each,
    // lane = column), pools adjacent columns with one shfl.
    #pragma unroll
    for (int t = 0; t < 4; t++) {
        const float* src = (t == 0) ? mu_a : (t == 1) ? lva : (t == 2) ? mu_b : lvb;
        const float scale = (t & 1) ? 0.0625f : 0.25f;   // var: sum4/16, mu: sum4/4
        #pragma unroll
        for (int i = 0; i < 2; i++) {
            const int b = warp + 16 * i;
            const int base = ((b * CC + c) * HH + 2 * y) * WW + lane;
            float l0 = src[base];
            float l1 = src[base + WW];
            if (t & 1) { l0 = __expf(l0); l1 = __expf(l1); }
            float s = l0 + l1;
            s += __shfl_xor_sync(0xFFFFFFFFu, s, 1);     // pair sum
            if ((lane & 1) == 0)
                pooled[t][b][lane >> 1] = s * scale;
        }
    }
    __syncthreads();

    // ---------- Phase 1b: per-(b,x) derived params ----------
    {
        const int b = tid >> 4;      // 0..31
        const int x = tid & 15;      // 0..15
        float m_a = pooled[0][b][x];
        float v_a = pooled[1][b][x];
        float m_b = pooled[2][b][x];
        float v_b = pooled[3][b][x];
        float e   = eps[((b * CC + c) * PH + y) * PW + x];

        const float NHALF_LOG2E = -0.7213475204444817f;  // -log2(e)/2
        float wa = rsqrtf(v_a);
        float z  = fmaf(v_a * wa, e, m_a);               // mu_a + sqrt(v_a)*eps
        float p_a = NHALF_LOG2E * wa * wa;               // coeff of z^2
        float q_a = -2.0f * p_a * m_a;                   // coeff of z
        float r_a = p_a * m_a * m_a;                     // const
        float wb = rsqrtf(v_b);
        float p_b = NHALF_LOG2E * wb * wb;
        float q_b = -2.0f * p_b * m_b;
        float r_b = p_b * m_b * m_b;

        pA[x][b] = make_float4(p_a, q_a, r_a, wa);
        pB[x][b] = make_float4(p_b, q_b, r_b, wb);
        zs[x][b] = z;
    }
    __syncthreads();

    // ---------- Phase 2: pairwise mixture densities (MUFU-bound) ----------
    // warp = x position, lane = sample index i
    {
        const int x = warp;
        float z  = zs[x][lane];
        float z2 = z * z;
        float sa = 0.f, sb = 0.f;
        #pragma unroll
        for (int j = 0; j < BB; j++) {
            float4 A = pA[x][j];   // broadcast LDS.128
            float4 Bp = pB[x][j];
            float arg_a = fmaf(A.x, z2, fmaf(A.y, z, A.z));
            sa = fmaf(A.w, ex2f(arg_a), sa);
            float arg_b = fmaf(Bp.x, z2, fmaf(Bp.y, z, Bp.z));
            sb = fmaf(Bp.w, ex2f(arg_b), sb);
        }
        const float LN2   = 0.6931471805599453f;
        const float EPSC  = 1e-6f;
        const float INV_B = 1.0f / (float)BB;
        float term = (lg2f(fmaf(sa, INV_B, EPSC)) -
                      lg2f(fmaf(sb, INV_B, EPSC))) * LN2;
        #pragma unroll
        for (int o = 16; o; o >>= 1)
            term += __shfl_xor_sync(0xFFFFFFFFu, term, o);
        if (lane == 0) wsum[warp] = term;
    }
    __syncthreads();

    // ---------- Block partial + last-block grid reduction ----------
    if (tid == 0) {
        double s = 0.0;
        #pragma unroll
        for (int w0 = 0; w0 < 16; w0++) s += (double)wsum[w0];
        g_partials[blockIdx.x] = s;
        __threadfence();
        unsigned int ticket = atomicInc(&g_count, NBLOCKS - 1);  // wraps to 0
        is_last_s = (ticket == NBLOCKS - 1);
    }
    __syncthreads();

    if (is_last_s) {
        // Deterministic fixed-order sum of all block partials.
        const volatile double* vp = g_partials;
        double s = 0.0;
        #pragma unroll
        for (int i = tid; i < NBLOCKS; i += NTHREADS)
            s += vp[i];
        dred[tid] = s;
        __syncthreads();
        #pragma unroll
        for (int o = NTHREADS / 2; o; o >>= 1) {
            if (tid < o) dred[tid] += dred[tid + o];
            __syncthreads();
        }
        if (tid == 0)
            out[0] = (float)((double)BB * dred[0]);
    }
}

extern "C" void kernel_launch(void* const* d_in, const int* in_sizes, int n_in,
                              void* d_out, int out_size)
{
    const float* mu_a = (const float*)d_in[0];
    const float* lva  = (const float*)d_in[1];
    const float* mu_b = (const float*)d_in[2];
    const float* lvb  = (const float*)d_in[3];
    const float* eps  = (const float*)d_in[4];
    gkl_kernel<<<NBLOCKS, NTHREADS>>>(mu_a, lva, mu_b, lvb, eps, (float*)d_out);
}